// round 14
// baseline (speedup 1.0000x reference)
#include <cuda_runtime.h>
#include <cuda_fp16.h>
#include <cstdint>

#define NUM_TOKENS 8192
#define HIDDEN 4096
#define NUM_EXPERTS 8
#define INTER 2048
#define GU_COLS 4096
#define MAX_TILES 72
#define NSTAGE 3

#define G1_BLOCKS 2304          /* 72 * 32 */
#define PW2_BLOCKS 4096         /* 8 * 32 * 16 */
#define G2_BLOCKS 2304
#define INTERLEAVED (G1_BLOCKS + PW2_BLOCKS)   /* 6400 = 256 groups of 25 (9 g1 + 16 pw2) */
#define MEGA_BLOCKS (INTERLEAVED + G2_BLOCKS)  /* 8704 */

#define PW1_BLOCKS 8192         /* 8 * 32 * 32 */
#define PX_BLOCKS  2304         /* 72 * 32 */

// ---------------- scratch ----------------
__device__ int g_counts[NUM_EXPERTS];
__device__ int g_lists[NUM_EXPERTS][NUM_TOKENS];
__device__ int g_is64;
__device__ int g_t1done[MAX_TILES];
__device__ int g_pwdone;
// fp16 A-fragment packed activations: [tile][kf16][mf 8][lane 32][4 b32]
__device__ uint32_t g_xpackh[(size_t)MAX_TILES * (HIDDEN / 16) * 8 * 32 * 4];
__device__ uint32_t g_interph[(size_t)MAX_TILES * (INTER / 16) * 8 * 32 * 4];
// fp16 B-fragment packed weights
__device__ uint32_t g_wp1[(size_t)NUM_EXPERTS * 32 * 256 * 2 * 8 * 32 * 2];
__device__ uint32_t g_wp2[(size_t)NUM_EXPERTS * 32 * 128 * 16 * 32 * 2];

// ---------------- helpers ----------------
__device__ __forceinline__ uint32_t smem_u32(const void* p) {
    uint32_t a;
    asm("{ .reg .u64 t; cvta.to.shared.u64 t, %1; cvt.u32.u64 %0, t; }" : "=r"(a) : "l"(p));
    return a;
}
__device__ __forceinline__ uint32_t f2h2(float lo, float hi) {
    __half2 h = __floats2half2_rn(lo, hi);
    return *(uint32_t*)&h;
}
__device__ __forceinline__ void mma16(float* d, const uint32_t* a, uint32_t b0, uint32_t b1) {
    asm volatile(
        "mma.sync.aligned.m16n8k16.row.col.f32.f16.f16.f32 "
        "{%0,%1,%2,%3},{%4,%5,%6,%7},{%8,%9},{%0,%1,%2,%3};"
        : "+f"(d[0]), "+f"(d[1]), "+f"(d[2]), "+f"(d[3])
        : "r"(a[0]), "r"(a[1]), "r"(a[2]), "r"(a[3]), "r"(b0), "r"(b1));
}
__device__ __forceinline__ void cpa16(uint32_t dst, const void* src) {
    asm volatile("cp.async.cg.shared.global [%0], [%1], 16;" :: "r"(dst), "l"(src));
}
__device__ __forceinline__ void cpa_commit() { asm volatile("cp.async.commit_group;" ::: "memory"); }
__device__ __forceinline__ void cpa_wait1()  { asm volatile("cp.async.wait_group 1;" ::: "memory"); }
__device__ __forceinline__ void cpa_wait0()  { asm volatile("cp.async.wait_group 0;" ::: "memory"); }

__device__ __forceinline__ float silu(float g) { return g / (1.0f + __expf(-g)); }

__device__ __forceinline__ int find_tile(int t, int* e_out, int* m0_out, int* cnt_out) {
    int acc = 0;
#pragma unroll
    for (int e = 0; e < NUM_EXPERTS; e++) {
        int c = g_counts[e];
        int nt = (c + 127) >> 7;
        if (t < acc + nt) { *e_out = e; *m0_out = (t - acc) << 7; *cnt_out = c; return 1; }
        acc += nt;
    }
    return 0;
}

// ---------------- routing ----------------
__global__ void detect_kernel(const int* __restrict__ t32) {
    if (threadIdx.x == 0) {
        int all_zero = 1;
        for (int i = 0; i < 256; i++) {
            int idx = 2 * (i * (NUM_TOKENS / 256)) + 1;
            if (t32[idx] != 0) { all_zero = 0; break; }
        }
        g_is64 = all_zero;
        g_pwdone = 0;
    }
    if (threadIdx.x < NUM_EXPERTS) g_counts[threadIdx.x] = 0;
    if (threadIdx.x < MAX_TILES) g_t1done[threadIdx.x] = 0;
}

__global__ void route_kernel(const int* __restrict__ t32) {
    int i = blockIdx.x * blockDim.x + threadIdx.x;
    if (i < NUM_TOKENS) {
        int v = g_is64 ? t32[2 * i] : t32[i];
        int e = v & 7;
        int p = atomicAdd(&g_counts[e], 1);
        g_lists[e][p] = i;
    }
}

// ---------------- prep kernel: pack_w1 + pack_x ----------------
#define PX_PITCH 132
#define PX_SMEM (128 * PX_PITCH * 4 + 512)

__device__ void pack_w1_body(const float* __restrict__ gup, int bx, int nt, int e) {
    const int tid = threadIdx.x;
    const int w = tid >> 5, lane = tid & 31;
    const int g = lane >> 2, tq = lane & 3;
    const int kf = bx * 8 + w;             // 0..255
    const float* W = gup + (size_t)e * HIDDEN * GU_COLS;
    const int k0 = kf * 16 + tq * 2;
#pragma unroll
    for (int i = 0; i < 16; i++) {
        int gu = i >> 3, nf = i & 7;
        int c = gu * INTER + nt * 64 + nf * 8 + g;
        const float* Wc = W + c;
        uint2 o;
        o.x = f2h2(Wc[(size_t)k0 * GU_COLS], Wc[(size_t)(k0 + 1) * GU_COLS]);
        o.y = f2h2(Wc[(size_t)(k0 + 8) * GU_COLS], Wc[(size_t)(k0 + 9) * GU_COLS]);
        size_t off = ((((((size_t)e * 32 + nt) * 256 + kf) * 2 + gu) * 8 + nf) * 32 + lane) * 2;
        *(uint2*)(g_wp1 + off) = o;
    }
}

__device__ void pack_x_body(const float* __restrict__ x, char* smem, int kb, int tile) {
    int e, m0, count;
    if (!find_tile(tile, &e, &m0, &count)) return;
    const int tid = threadIdx.x;
    int* tokS = (int*)smem;
    float* tsm = (float*)(smem + 512);
    if (tid < 128) tokS[tid] = (m0 + tid < count) ? g_lists[e][m0 + tid] : -1;
    __syncthreads();
#pragma unroll
    for (int j = 0; j < 16; j++) {
        int idx = tid + j * 256;
        int r = idx >> 5, c4 = (idx & 31) * 4;
        int t = tokS[r];
        float4 v = make_float4(0.f, 0.f, 0.f, 0.f);
        if (t >= 0) v = *(const float4*)(x + (size_t)t * HIDDEN + kb * 128 + c4);
        *(float4*)(tsm + r * PX_PITCH + c4) = v;
    }
    __syncthreads();
    const int lane = tid & 31, w = tid >> 5;
    const int g = lane >> 2, tq = lane & 3;
    const int kf = kb * 8 + w;
#pragma unroll
    for (int mf = 0; mf < 8; mf++) {
        int r0 = mf * 16 + g;
        int c0 = w * 16 + 2 * tq;
        float2 v00 = *(float2*)(tsm + r0 * PX_PITCH + c0);
        float2 v10 = *(float2*)(tsm + (r0 + 8) * PX_PITCH + c0);
        float2 v01 = *(float2*)(tsm + r0 * PX_PITCH + c0 + 8);
        float2 v11 = *(float2*)(tsm + (r0 + 8) * PX_PITCH + c0 + 8);
        uint4 o;
        o.x = f2h2(v00.x, v00.y);
        o.y = f2h2(v10.x, v10.y);
        o.z = f2h2(v01.x, v01.y);
        o.w = f2h2(v11.x, v11.y);
        size_t off = ((((size_t)tile * (HIDDEN / 16) + kf) * 8 + mf) * 32 + lane) * 4;
        *(uint4*)(g_xpackh + off) = o;
    }
}

__global__ __launch_bounds__(256) void prep_kernel(const float* __restrict__ gup,
                                                   const float* __restrict__ x) {
    extern __shared__ char smem[];
    int fid = blockIdx.x;
    if (fid < PW1_BLOCKS) {
        pack_w1_body(gup, fid & 31, (fid >> 5) & 31, fid >> 10);
    } else {
        int idx = fid - PW1_BLOCKS;
        pack_x_body(x, smem, idx & 31, idx >> 5);
    }
}

// smem: per stage [A 16KB][B 16KB], BK=64 (4 kf16)
#define STAGE_BYTES 32768
#define GEMM_SMEM (NSTAGE * STAGE_BYTES)   /* 98304 */

// ---------------- mega kernel bodies ----------------
__device__ void pack_w2_body(const float* __restrict__ down, int idx) {
    const int bx = idx & 15, nt = (idx >> 4) & 31, e = idx >> 9;
    const int tid = threadIdx.x;
    const int w = tid >> 5, lane = tid & 31;
    const int g = lane >> 2, tq = lane & 3;
    const int kf = bx * 8 + w;             // 0..127
    const float* W = down + (size_t)e * INTER * HIDDEN;
    const int k0 = kf * 16 + tq * 2;
#pragma unroll
    for (int nf = 0; nf < 16; nf++) {
        int c = nt * 128 + nf * 8 + g;
        const float* Wc = W + c;
        uint2 o;
        o.x = f2h2(Wc[(size_t)k0 * HIDDEN], Wc[(size_t)(k0 + 1) * HIDDEN]);
        o.y = f2h2(Wc[(size_t)(k0 + 8) * HIDDEN], Wc[(size_t)(k0 + 9) * HIDDEN]);
        size_t off = (((((size_t)e * 32 + nt) * 128 + kf) * 16 + nf) * 32 + lane) * 2;
        *(uint2*)(g_wp2 + off) = o;
    }
    __threadfence();
    __syncthreads();
    if (tid == 0) atomicAdd(&g_pwdone, 1);
}

__device__ void gemm1_body(char* smem, int nt, int t_id) {
    int e, m0, count;
    if (!find_tile(t_id, &e, &m0, &count)) return;

    const uint32_t sb = smem_u32(smem);
    const int tid = threadIdx.x;
    const int wid = tid >> 5, lane = tid & 31;
    const int mw = wid >> 2, nw = wid & 3;
    const int g = lane >> 2, tq = lane & 3;

    const uint32_t* xA = g_xpackh + (size_t)t_id * (HIDDEN / 16) * 1024;
    const uint32_t* wB = g_wp1 + (((size_t)e * 32 + nt) * 256) * 1024;

    auto issue = [&](int kc, int soff) {
        const uint32_t* As = xA + (size_t)kc * 4096;
        const uint32_t* Bs = wB + (size_t)kc * 4096;
#pragma unroll
        for (int j = 0; j < 4; j++) {
            int idx = tid + j * 256;
            cpa16(sb + soff + idx * 16, As + idx * 4);
            cpa16(sb + soff + 16384 + idx * 16, Bs + idx * 4);
        }
    };

    float accg[4][2][4] = {};
    float accu[4][2][4] = {};

    issue(0, 0);
    cpa_commit();
    issue(1, STAGE_BYTES);
    cpa_commit();

    const int NK = HIDDEN / 64;
    int soff_c = 0, soff_p = 2 * STAGE_BYTES;
    for (int kc = 0; kc < NK; kc++) {
        if (kc + 1 < NK) cpa_wait1(); else cpa_wait0();
        __syncthreads();
        if (kc + 2 < NK) {
            issue(kc + 2, soff_p);
            cpa_commit();
        }

#pragma unroll
        for (int kk = 0; kk < 4; kk++) {
            uint2 bg[2], bu[2];
#pragma unroll
            for (int ni = 0; ni < 2; ni++) {
                bg[ni] = *(const uint2*)(smem + soff_c + 16384 +
                            ((kk * 2 + 0) * 8 + nw * 2 + ni) * 256 + lane * 8);
                bu[ni] = *(const uint2*)(smem + soff_c + 16384 +
                            ((kk * 2 + 1) * 8 + nw * 2 + ni) * 256 + lane * 8);
            }
#pragma unroll
            for (int mi = 0; mi < 4; mi++) {
                const uint4 a = *(const uint4*)(smem + soff_c +
                            ((kk * 8 + mw * 4 + mi) * 32 + lane) * 16);
                mma16(accg[mi][0], &a.x, bg[0].x, bg[0].y);
                mma16(accg[mi][1], &a.x, bg[1].x, bg[1].y);
                mma16(accu[mi][0], &a.x, bu[0].x, bu[0].y);
                mma16(accu[mi][1], &a.x, bu[1].x, bu[1].y);
            }
        }
        soff_c += STAGE_BYTES; if (soff_c == NSTAGE * STAGE_BYTES) soff_c = 0;
        soff_p += STAGE_BYTES; if (soff_p == NSTAGE * STAGE_BYTES) soff_p = 0;
    }

    const int kf = nt * 4 + nw;
#pragma unroll
    for (int mi = 0; mi < 4; mi++) {
        int mf = mw * 4 + mi;
        uint4 o;
        {
            float v0 = silu(accg[mi][0][0]) * accu[mi][0][0];
            float v1 = silu(accg[mi][0][1]) * accu[mi][0][1];
            float v2 = silu(accg[mi][0][2]) * accu[mi][0][2];
            float v3 = silu(accg[mi][0][3]) * accu[mi][0][3];
            o.x = f2h2(v0, v1);
            o.y = f2h2(v2, v3);
        }
        {
            float v0 = silu(accg[mi][1][0]) * accu[mi][1][0];
            float v1 = silu(accg[mi][1][1]) * accu[mi][1][1];
            float v2 = silu(accg[mi][1][2]) * accu[mi][1][2];
            float v3 = silu(accg[mi][1][3]) * accu[mi][1][3];
            o.z = f2h2(v0, v1);
            o.w = f2h2(v2, v3);
        }
        size_t off = ((((size_t)t_id * (INTER / 16) + kf) * 8 + mf) * 32 + (g * 4 + tq)) * 4;
        *(uint4*)(g_interph + off) = o;
    }

    __threadfence();
    __syncthreads();
    if (tid == 0) atomicAdd(&g_t1done[t_id], 1);
}

__device__ void gemm2_body(char* smem, int* tokS, float* __restrict__ out, int nt, int t_id) {
    int e, m0, count;
    if (!find_tile(t_id, &e, &m0, &count)) return;
    const int n0 = nt * 128;

    const uint32_t sb = smem_u32(smem);
    const int tid = threadIdx.x;
    const int wid = tid >> 5, lane = tid & 31;
    const int mw = wid >> 2, nw = wid & 3;
    const int g = lane >> 2, tq = lane & 3;

    // wait for pack_w2 completion and this tile's gemm1 blocks
    if (tid == 0) {
        while (atomicAdd(&g_pwdone, 0) < PW2_BLOCKS) {}
        while (atomicAdd(&g_t1done[t_id], 0) < 32) {}
        __threadfence();
    }
    if (tid < 128) {
        // safe to read after spin completes at syncthreads below
    }
    __syncthreads();
    if (tid < 128) tokS[tid] = (m0 + tid < count) ? g_lists[e][m0 + tid] : -1;
    __syncthreads();

    const uint32_t* xA = g_interph + (size_t)t_id * (INTER / 16) * 1024;
    const uint32_t* wB = g_wp2 + (((size_t)e * 32 + nt) * 128) * 1024;

    auto issue = [&](int kc, int soff) {
        const uint32_t* As = xA + (size_t)kc * 4096;
        const uint32_t* Bs = wB + (size_t)kc * 4096;
#pragma unroll
        for (int j = 0; j < 4; j++) {
            int idx = tid + j * 256;
            cpa16(sb + soff + idx * 16, As + idx * 4);
            cpa16(sb + soff + 16384 + idx * 16, Bs + idx * 4);
        }
    };

    float acc[4][4][4] = {};

    issue(0, 0);
    cpa_commit();
    issue(1, STAGE_BYTES);
    cpa_commit();

    const int NK = INTER / 64;
    int soff_c = 0, soff_p = 2 * STAGE_BYTES;
    for (int kc = 0; kc < NK; kc++) {
        if (kc + 1 < NK) cpa_wait1(); else cpa_wait0();
        __syncthreads();
        if (kc + 2 < NK) {
            issue(kc + 2, soff_p);
            cpa_commit();
        }

#pragma unroll
        for (int kk = 0; kk < 4; kk++) {
            uint2 bb[4];
#pragma unroll
            for (int ni = 0; ni < 4; ni++)
                bb[ni] = *(const uint2*)(smem + soff_c + 16384 +
                            (kk * 16 + nw * 4 + ni) * 256 + lane * 8);
#pragma unroll
            for (int mi = 0; mi < 4; mi++) {
                const uint4 a = *(const uint4*)(smem + soff_c +
                            ((kk * 8 + mw * 4 + mi) * 32 + lane) * 16);
#pragma unroll
                for (int ni = 0; ni < 4; ni++)
                    mma16(acc[mi][ni], &a.x, bb[ni].x, bb[ni].y);
            }
        }
        soff_c += STAGE_BYTES; if (soff_c == NSTAGE * STAGE_BYTES) soff_c = 0;
        soff_p += STAGE_BYTES; if (soff_p == NSTAGE * STAGE_BYTES) soff_p = 0;
    }

#pragma unroll
    for (int mi = 0; mi < 4; mi++) {
        int r0 = mw * 64 + mi * 16 + g;
        int t0 = tokS[r0], t1 = tokS[r0 + 8];
#pragma unroll
        for (int ni = 0; ni < 4; ni++) {
            int col = n0 + nw * 32 + ni * 8 + 2 * tq;
            if (t0 >= 0)
                *(float2*)(out + (size_t)t0 * HIDDEN + col) =
                    make_float2(acc[mi][ni][0], acc[mi][ni][1]);
            if (t1 >= 0)
                *(float2*)(out + (size_t)t1 * HIDDEN + col) =
                    make_float2(acc[mi][ni][2], acc[mi][ni][3]);
        }
    }
}

// ---------------- mega kernel: pack_w2 (interleaved with) gemm1, then gemm2 ----------------
__global__ __launch_bounds__(256, 2) void mega_kernel(const float* __restrict__ down,
                                                      float* __restrict__ out) {
    extern __shared__ char smem[];
    __shared__ int tokS[128];
    const int fid = blockIdx.x;
    if (fid < INTERLEAVED) {
        const int grp = fid / 25, r = fid % 25;
        if (r < 9) {
            const int idx = grp * 9 + r;             // 0..2303
            gemm1_body(smem, idx & 31, idx >> 5);
        } else {
            const int idx = grp * 16 + (r - 9);      // 0..4095
            pack_w2_body(down, idx);
        }
    } else {
        const int idx = fid - INTERLEAVED;           // 0..2303
        gemm2_body(smem, tokS, out, idx & 31, idx >> 5);
    }
}

// ---------------- launch ----------------
extern "C" void kernel_launch(void* const* d_in, const int* in_sizes, int n_in,
                              void* d_out, int out_size) {
    const float* x    = (const float*)d_in[0];
    const int*   tids = (const int*)d_in[1];
    const float* gup  = (const float*)d_in[2];
    const float* down = (const float*)d_in[3];
    float*       out  = (float*)d_out;

    cudaFuncSetAttribute(prep_kernel, cudaFuncAttributeMaxDynamicSharedMemorySize, PX_SMEM);
    cudaFuncSetAttribute(mega_kernel, cudaFuncAttributeMaxDynamicSharedMemorySize, GEMM_SMEM);

    detect_kernel<<<1, 128>>>(tids);
    route_kernel<<<NUM_TOKENS / 256, 256>>>(tids);
    prep_kernel<<<PW1_BLOCKS + PX_BLOCKS, 256, PX_SMEM>>>(gup, x);
    mega_kernel<<<MEGA_BLOCKS, 256, GEMM_SMEM>>>(down, out);
}

// round 15
// speedup vs baseline: 1.0569x; 1.0569x over previous
#include <cuda_runtime.h>
#include <cuda_fp16.h>
#include <cstdint>

#define NUM_TOKENS 8192
#define HIDDEN 4096
#define NUM_EXPERTS 8
#define INTER 2048
#define GU_COLS 4096
#define MAX_TILES 72
#define NSTAGE 3

#define G1_BLOCKS 2304          /* 72 * 32 */
#define PW2_BLOCKS 4096         /* 8 * 32 * 16 */
#define G2_BLOCKS 2304
#define INTERLEAVED (G1_BLOCKS + PW2_BLOCKS)   /* 6400 = 256 groups of 25 (9 g1 + 16 pw2) */
#define MEGA_BLOCKS (INTERLEAVED + G2_BLOCKS)  /* 8704 */

// ---------------- scratch ----------------
__device__ int g_counts[NUM_EXPERTS];
__device__ int g_lists[NUM_EXPERTS][NUM_TOKENS];
__device__ int g_is64;
__device__ int g_t1done[MAX_TILES];
__device__ int g_pwdone;
// fp16 A-fragment packed activations: [tile][kf16][mf 8][lane 32][4 b32]
__device__ uint32_t g_xpackh[(size_t)MAX_TILES * (HIDDEN / 16) * 8 * 32 * 4];
__device__ uint32_t g_interph[(size_t)MAX_TILES * (INTER / 16) * 8 * 32 * 4];
// fp16 B-fragment packed weights
__device__ uint32_t g_wp1[(size_t)NUM_EXPERTS * 32 * 256 * 2 * 8 * 32 * 2];
__device__ uint32_t g_wp2[(size_t)NUM_EXPERTS * 32 * 128 * 16 * 32 * 2];

// ---------------- helpers ----------------
__device__ __forceinline__ uint32_t smem_u32(const void* p) {
    uint32_t a;
    asm("{ .reg .u64 t; cvta.to.shared.u64 t, %1; cvt.u32.u64 %0, t; }" : "=r"(a) : "l"(p));
    return a;
}
__device__ __forceinline__ uint32_t f2h2(float lo, float hi) {
    __half2 h = __floats2half2_rn(lo, hi);
    return *(uint32_t*)&h;
}
__device__ __forceinline__ void mma16(float* d, const uint32_t* a, uint32_t b0, uint32_t b1) {
    asm volatile(
        "mma.sync.aligned.m16n8k16.row.col.f32.f16.f16.f32 "
        "{%0,%1,%2,%3},{%4,%5,%6,%7},{%8,%9},{%0,%1,%2,%3};"
        : "+f"(d[0]), "+f"(d[1]), "+f"(d[2]), "+f"(d[3])
        : "r"(a[0]), "r"(a[1]), "r"(a[2]), "r"(a[3]), "r"(b0), "r"(b1));
}
__device__ __forceinline__ void cpa16(uint32_t dst, const void* src) {
    asm volatile("cp.async.cg.shared.global [%0], [%1], 16;" :: "r"(dst), "l"(src));
}
__device__ __forceinline__ void cpa_commit() { asm volatile("cp.async.commit_group;" ::: "memory"); }
__device__ __forceinline__ void cpa_wait1()  { asm volatile("cp.async.wait_group 1;" ::: "memory"); }
__device__ __forceinline__ void cpa_wait0()  { asm volatile("cp.async.wait_group 0;" ::: "memory"); }

__device__ __forceinline__ float silu(float g) { return g / (1.0f + __expf(-g)); }

__device__ __forceinline__ int find_tile(int t, int* e_out, int* m0_out, int* cnt_out) {
    int acc = 0;
#pragma unroll
    for (int e = 0; e < NUM_EXPERTS; e++) {
        int c = g_counts[e];
        int nt = (c + 127) >> 7;
        if (t < acc + nt) { *e_out = e; *m0_out = (t - acc) << 7; *cnt_out = c; return 1; }
        acc += nt;
    }
    return 0;
}

// ---------------- routing ----------------
__global__ void detect_kernel(const int* __restrict__ t32) {
    if (threadIdx.x == 0) {
        int all_zero = 1;
        for (int i = 0; i < 256; i++) {
            int idx = 2 * (i * (NUM_TOKENS / 256)) + 1;
            if (t32[idx] != 0) { all_zero = 0; break; }
        }
        g_is64 = all_zero;
        g_pwdone = 0;
    }
    if (threadIdx.x < NUM_EXPERTS) g_counts[threadIdx.x] = 0;
    if (threadIdx.x < MAX_TILES) g_t1done[threadIdx.x] = 0;
}

__global__ void route_kernel(const int* __restrict__ t32) {
    int i = blockIdx.x * blockDim.x + threadIdx.x;
    if (i < NUM_TOKENS) {
        int v = g_is64 ? t32[2 * i] : t32[i];
        int e = v & 7;
        int p = atomicAdd(&g_counts[e], 1);
        g_lists[e][p] = i;
    }
}

// ---------------- pack_w1 (standalone, no dynamic smem -> full occupancy) ----------------
__global__ __launch_bounds__(256) void pack_w1_kernel(const float* __restrict__ gup) {
    const int e = blockIdx.z, nt = blockIdx.y;
    const int tid = threadIdx.x;
    const int w = tid >> 5, lane = tid & 31;
    const int g = lane >> 2, tq = lane & 3;
    const int kf = blockIdx.x * 8 + w;     // 0..255
    const float* W = gup + (size_t)e * HIDDEN * GU_COLS;
    const int k0 = kf * 16 + tq * 2;
#pragma unroll
    for (int i = 0; i < 16; i++) {
        int gu = i >> 3, nf = i & 7;
        int c = gu * INTER + nt * 64 + nf * 8 + g;
        const float* Wc = W + c;
        uint2 o;
        o.x = f2h2(Wc[(size_t)k0 * GU_COLS], Wc[(size_t)(k0 + 1) * GU_COLS]);
        o.y = f2h2(Wc[(size_t)(k0 + 8) * GU_COLS], Wc[(size_t)(k0 + 9) * GU_COLS]);
        size_t off = ((((((size_t)e * 32 + nt) * 256 + kf) * 2 + gu) * 8 + nf) * 32 + lane) * 2;
        *(uint2*)(g_wp1 + off) = o;
    }
}

// ---------------- pack_x (standalone) ----------------
#define PX_PITCH 132
#define PX_SMEM (128 * PX_PITCH * 4 + 512)
__global__ __launch_bounds__(256) void pack_x_kernel(const float* __restrict__ x) {
    extern __shared__ char smem[];
    int e, m0, count;
    if (!find_tile(blockIdx.y, &e, &m0, &count)) return;
    const int kb = blockIdx.x;
    const int tid = threadIdx.x;
    int* tokS = (int*)smem;
    float* tsm = (float*)(smem + 512);
    if (tid < 128) tokS[tid] = (m0 + tid < count) ? g_lists[e][m0 + tid] : -1;
    __syncthreads();
#pragma unroll
    for (int j = 0; j < 16; j++) {
        int idx = tid + j * 256;
        int r = idx >> 5, c4 = (idx & 31) * 4;
        int t = tokS[r];
        float4 v = make_float4(0.f, 0.f, 0.f, 0.f);
        if (t >= 0) v = *(const float4*)(x + (size_t)t * HIDDEN + kb * 128 + c4);
        *(float4*)(tsm + r * PX_PITCH + c4) = v;
    }
    __syncthreads();
    const int lane = tid & 31, w = tid >> 5;
    const int g = lane >> 2, tq = lane & 3;
    const int kf = kb * 8 + w;
#pragma unroll
    for (int mf = 0; mf < 8; mf++) {
        int r0 = mf * 16 + g;
        int c0 = w * 16 + 2 * tq;
        float2 v00 = *(float2*)(tsm + r0 * PX_PITCH + c0);
        float2 v10 = *(float2*)(tsm + (r0 + 8) * PX_PITCH + c0);
        float2 v01 = *(float2*)(tsm + r0 * PX_PITCH + c0 + 8);
        float2 v11 = *(float2*)(tsm + (r0 + 8) * PX_PITCH + c0 + 8);
        uint4 o;
        o.x = f2h2(v00.x, v00.y);
        o.y = f2h2(v10.x, v10.y);
        o.z = f2h2(v01.x, v01.y);
        o.w = f2h2(v11.x, v11.y);
        size_t off = ((((size_t)blockIdx.y * (HIDDEN / 16) + kf) * 8 + mf) * 32 + lane) * 4;
        *(uint4*)(g_xpackh + off) = o;
    }
}

// smem: per stage [A 16KB][B 16KB], BK=64 (4 kf16)
#define STAGE_BYTES 32768
#define GEMM_SMEM (NSTAGE * STAGE_BYTES)   /* 98304 */

// ---------------- mega kernel bodies ----------------
__device__ void pack_w2_body(const float* __restrict__ down, int idx) {
    const int bx = idx & 15, nt = (idx >> 4) & 31, e = idx >> 9;
    const int tid = threadIdx.x;
    const int w = tid >> 5, lane = tid & 31;
    const int g = lane >> 2, tq = lane & 3;
    const int kf = bx * 8 + w;             // 0..127
    const float* W = down + (size_t)e * INTER * HIDDEN;
    const int k0 = kf * 16 + tq * 2;
#pragma unroll
    for (int nf = 0; nf < 16; nf++) {
        int c = nt * 128 + nf * 8 + g;
        const float* Wc = W + c;
        uint2 o;
        o.x = f2h2(Wc[(size_t)k0 * HIDDEN], Wc[(size_t)(k0 + 1) * HIDDEN]);
        o.y = f2h2(Wc[(size_t)(k0 + 8) * HIDDEN], Wc[(size_t)(k0 + 9) * HIDDEN]);
        size_t off = (((((size_t)e * 32 + nt) * 128 + kf) * 16 + nf) * 32 + lane) * 2;
        *(uint2*)(g_wp2 + off) = o;
    }
    __threadfence();
    __syncthreads();
    if (tid == 0) atomicAdd(&g_pwdone, 1);
}

__device__ void gemm1_body(char* smem, int nt, int t_id) {
    int e, m0, count;
    if (!find_tile(t_id, &e, &m0, &count)) return;

    const uint32_t sb = smem_u32(smem);
    const int tid = threadIdx.x;
    const int wid = tid >> 5, lane = tid & 31;
    const int mw = wid >> 2, nw = wid & 3;
    const int g = lane >> 2, tq = lane & 3;

    const uint32_t* xA = g_xpackh + (size_t)t_id * (HIDDEN / 16) * 1024;
    const uint32_t* wB = g_wp1 + (((size_t)e * 32 + nt) * 256) * 1024;

    auto issue = [&](int kc, int soff) {
        const uint32_t* As = xA + (size_t)kc * 4096;
        const uint32_t* Bs = wB + (size_t)kc * 4096;
#pragma unroll
        for (int j = 0; j < 4; j++) {
            int idx = tid + j * 256;
            cpa16(sb + soff + idx * 16, As + idx * 4);
            cpa16(sb + soff + 16384 + idx * 16, Bs + idx * 4);
        }
    };

    float accg[4][2][4] = {};
    float accu[4][2][4] = {};

    issue(0, 0);
    cpa_commit();
    issue(1, STAGE_BYTES);
    cpa_commit();

    const int NK = HIDDEN / 64;
    int soff_c = 0, soff_p = 2 * STAGE_BYTES;
    for (int kc = 0; kc < NK; kc++) {
        if (kc + 1 < NK) cpa_wait1(); else cpa_wait0();
        __syncthreads();
        if (kc + 2 < NK) {
            issue(kc + 2, soff_p);
            cpa_commit();
        }

#pragma unroll
        for (int kk = 0; kk < 4; kk++) {
            uint2 bg[2], bu[2];
#pragma unroll
            for (int ni = 0; ni < 2; ni++) {
                bg[ni] = *(const uint2*)(smem + soff_c + 16384 +
                            ((kk * 2 + 0) * 8 + nw * 2 + ni) * 256 + lane * 8);
                bu[ni] = *(const uint2*)(smem + soff_c + 16384 +
                            ((kk * 2 + 1) * 8 + nw * 2 + ni) * 256 + lane * 8);
            }
#pragma unroll
            for (int mi = 0; mi < 4; mi++) {
                const uint4 a = *(const uint4*)(smem + soff_c +
                            ((kk * 8 + mw * 4 + mi) * 32 + lane) * 16);
                mma16(accg[mi][0], &a.x, bg[0].x, bg[0].y);
                mma16(accg[mi][1], &a.x, bg[1].x, bg[1].y);
                mma16(accu[mi][0], &a.x, bu[0].x, bu[0].y);
                mma16(accu[mi][1], &a.x, bu[1].x, bu[1].y);
            }
        }
        soff_c += STAGE_BYTES; if (soff_c == NSTAGE * STAGE_BYTES) soff_c = 0;
        soff_p += STAGE_BYTES; if (soff_p == NSTAGE * STAGE_BYTES) soff_p = 0;
    }

    const int kf = nt * 4 + nw;
#pragma unroll
    for (int mi = 0; mi < 4; mi++) {
        int mf = mw * 4 + mi;
        uint4 o;
        {
            float v0 = silu(accg[mi][0][0]) * accu[mi][0][0];
            float v1 = silu(accg[mi][0][1]) * accu[mi][0][1];
            float v2 = silu(accg[mi][0][2]) * accu[mi][0][2];
            float v3 = silu(accg[mi][0][3]) * accu[mi][0][3];
            o.x = f2h2(v0, v1);
            o.y = f2h2(v2, v3);
        }
        {
            float v0 = silu(accg[mi][1][0]) * accu[mi][1][0];
            float v1 = silu(accg[mi][1][1]) * accu[mi][1][1];
            float v2 = silu(accg[mi][1][2]) * accu[mi][1][2];
            float v3 = silu(accg[mi][1][3]) * accu[mi][1][3];
            o.z = f2h2(v0, v1);
            o.w = f2h2(v2, v3);
        }
        size_t off = ((((size_t)t_id * (INTER / 16) + kf) * 8 + mf) * 32 + (g * 4 + tq)) * 4;
        *(uint4*)(g_interph + off) = o;
    }

    __threadfence();
    __syncthreads();
    if (tid == 0) atomicAdd(&g_t1done[t_id], 1);
}

__device__ void gemm2_body(char* smem, int* tokS, float* __restrict__ out, int nt, int t_id) {
    int e, m0, count;
    if (!find_tile(t_id, &e, &m0, &count)) return;
    const int n0 = nt * 128;

    const uint32_t sb = smem_u32(smem);
    const int tid = threadIdx.x;
    const int wid = tid >> 5, lane = tid & 31;
    const int mw = wid >> 2, nw = wid & 3;
    const int g = lane >> 2, tq = lane & 3;

    if (tid == 0) {
        while (atomicAdd(&g_pwdone, 0) < PW2_BLOCKS) {}
        while (atomicAdd(&g_t1done[t_id], 0) < 32) {}
        __threadfence();
    }
    __syncthreads();
    if (tid < 128) tokS[tid] = (m0 + tid < count) ? g_lists[e][m0 + tid] : -1;
    __syncthreads();

    const uint32_t* xA = g_interph + (size_t)t_id * (INTER / 16) * 1024;
    const uint32_t* wB = g_wp2 + (((size_t)e * 32 + nt) * 128) * 1024;

    auto issue = [&](int kc, int soff) {
        const uint32_t* As = xA + (size_t)kc * 4096;
        const uint32_t* Bs = wB + (size_t)kc * 4096;
#pragma unroll
        for (int j = 0; j < 4; j++) {
            int idx = tid + j * 256;
            cpa16(sb + soff + idx * 16, As + idx * 4);
            cpa16(sb + soff + 16384 + idx * 16, Bs + idx * 4);
        }
    };

    float acc[4][4][4] = {};

    issue(0, 0);
    cpa_commit();
    issue(1, STAGE_BYTES);
    cpa_commit();

    const int NK = INTER / 64;
    int soff_c = 0, soff_p = 2 * STAGE_BYTES;
    for (int kc = 0; kc < NK; kc++) {
        if (kc + 1 < NK) cpa_wait1(); else cpa_wait0();
        __syncthreads();
        if (kc + 2 < NK) {
            issue(kc + 2, soff_p);
            cpa_commit();
        }

#pragma unroll
        for (int kk = 0; kk < 4; kk++) {
            uint2 bb[4];
#pragma unroll
            for (int ni = 0; ni < 4; ni++)
                bb[ni] = *(const uint2*)(smem + soff_c + 16384 +
                            (kk * 16 + nw * 4 + ni) * 256 + lane * 8);
#pragma unroll
            for (int mi = 0; mi < 4; mi++) {
                const uint4 a = *(const uint4*)(smem + soff_c +
                            ((kk * 8 + mw * 4 + mi) * 32 + lane) * 16);
#pragma unroll
                for (int ni = 0; ni < 4; ni++)
                    mma16(acc[mi][ni], &a.x, bb[ni].x, bb[ni].y);
            }
        }
        soff_c += STAGE_BYTES; if (soff_c == NSTAGE * STAGE_BYTES) soff_c = 0;
        soff_p += STAGE_BYTES; if (soff_p == NSTAGE * STAGE_BYTES) soff_p = 0;
    }

#pragma unroll
    for (int mi = 0; mi < 4; mi++) {
        int r0 = mw * 64 + mi * 16 + g;
        int t0 = tokS[r0], t1 = tokS[r0 + 8];
#pragma unroll
        for (int ni = 0; ni < 4; ni++) {
            int col = n0 + nw * 32 + ni * 8 + 2 * tq;
            if (t0 >= 0)
                *(float2*)(out + (size_t)t0 * HIDDEN + col) =
                    make_float2(acc[mi][ni][0], acc[mi][ni][1]);
            if (t1 >= 0)
                *(float2*)(out + (size_t)t1 * HIDDEN + col) =
                    make_float2(acc[mi][ni][2], acc[mi][ni][3]);
        }
    }
}

// ---------------- mega kernel: pack_w2 (interleaved with) gemm1, then gemm2 ----------------
__global__ __launch_bounds__(256, 2) void mega_kernel(const float* __restrict__ down,
                                                      float* __restrict__ out) {
    extern __shared__ char smem[];
    __shared__ int tokS[128];
    const int fid = blockIdx.x;
    if (fid < INTERLEAVED) {
        const int grp = fid / 25, r = fid % 25;
        if (r < 9) {
            const int idx = grp * 9 + r;             // 0..2303
            gemm1_body(smem, idx & 31, idx >> 5);
        } else {
            const int idx = grp * 16 + (r - 9);      // 0..4095
            pack_w2_body(down, idx);
        }
    } else {
        const int idx = fid - INTERLEAVED;           // 0..2303
        gemm2_body(smem, tokS, out, idx & 31, idx >> 5);
    }
}

// ---------------- launch ----------------
extern "C" void kernel_launch(void* const* d_in, const int* in_sizes, int n_in,
                              void* d_out, int out_size) {
    const float* x    = (const float*)d_in[0];
    const int*   tids = (const int*)d_in[1];
    const float* gup  = (const float*)d_in[2];
    const float* down = (const float*)d_in[3];
    float*       out  = (float*)d_out;

    cudaFuncSetAttribute(pack_x_kernel, cudaFuncAttributeMaxDynamicSharedMemorySize, PX_SMEM);
    cudaFuncSetAttribute(mega_kernel, cudaFuncAttributeMaxDynamicSharedMemorySize, GEMM_SMEM);

    detect_kernel<<<1, 128>>>(tids);
    route_kernel<<<NUM_TOKENS / 256, 256>>>(tids);
    pack_w1_kernel<<<dim3(32, 32, NUM_EXPERTS), 256>>>(gup);       // no dynamic smem
    pack_x_kernel<<<dim3(HIDDEN / 128, MAX_TILES), 256, PX_SMEM>>>(x);
    mega_kernel<<<MEGA_BLOCKS, 256, GEMM_SMEM>>>(down, out);
}

// round 16
// speedup vs baseline: 1.0889x; 1.0303x over previous
#include <cuda_runtime.h>
#include <cuda_fp16.h>
#include <cstdint>

#define NUM_TOKENS 8192
#define HIDDEN 4096
#define NUM_EXPERTS 8
#define INTER 2048
#define GU_COLS 4096
#define MAX_TILES 72
#define NSTAGE 3

#define G1_BLOCKS 2304          /* 72 * 32 */
#define PW2_BLOCKS 4096         /* 8 * 32 * 16 */
#define G2_BLOCKS 2304
#define INTERLEAVED (G1_BLOCKS + PW2_BLOCKS)   /* 6400 = 256 groups of 25 (9 g1 + 16 pw2) */
#define MEGA_BLOCKS (INTERLEAVED + G2_BLOCKS)  /* 8704 */

#define PW1_BLOCKS 8192         /* 8e * 32nt * 32kb */
#define PX_BLOCKS  2304         /* 72 * 32 */

// ---------------- scratch ----------------
__device__ int g_counts[NUM_EXPERTS];
__device__ int g_lists[NUM_EXPERTS][NUM_TOKENS];
__device__ int g_is64;
__device__ int g_t1done[MAX_TILES];
__device__ int g_pwdone;
// fp16 A-fragment packed activations: [tile][kf16][mf 8][lane 32][4 b32]
__device__ uint32_t g_xpackh[(size_t)MAX_TILES * (HIDDEN / 16) * 8 * 32 * 4];
__device__ uint32_t g_interph[(size_t)MAX_TILES * (INTER / 16) * 8 * 32 * 4];
// fp16 B-fragment packed weights
__device__ uint32_t g_wp1[(size_t)NUM_EXPERTS * 32 * 256 * 2 * 8 * 32 * 2];
__device__ uint32_t g_wp2[(size_t)NUM_EXPERTS * 32 * 128 * 16 * 32 * 2];

// ---------------- helpers ----------------
__device__ __forceinline__ uint32_t smem_u32(const void* p) {
    uint32_t a;
    asm("{ .reg .u64 t; cvta.to.shared.u64 t, %1; cvt.u32.u64 %0, t; }" : "=r"(a) : "l"(p));
    return a;
}
__device__ __forceinline__ uint32_t f2h2(float lo, float hi) {
    __half2 h = __floats2half2_rn(lo, hi);
    return *(uint32_t*)&h;
}
__device__ __forceinline__ void mma16(float* d, const uint32_t* a, uint32_t b0, uint32_t b1) {
    asm volatile(
        "mma.sync.aligned.m16n8k16.row.col.f32.f16.f16.f32 "
        "{%0,%1,%2,%3},{%4,%5,%6,%7},{%8,%9},{%0,%1,%2,%3};"
        : "+f"(d[0]), "+f"(d[1]), "+f"(d[2]), "+f"(d[3])
        : "r"(a[0]), "r"(a[1]), "r"(a[2]), "r"(a[3]), "r"(b0), "r"(b1));
}
__device__ __forceinline__ void cpa16(uint32_t dst, const void* src) {
    asm volatile("cp.async.cg.shared.global [%0], [%1], 16;" :: "r"(dst), "l"(src));
}
__device__ __forceinline__ void cpa_commit() { asm volatile("cp.async.commit_group;" ::: "memory"); }
__device__ __forceinline__ void cpa_wait1()  { asm volatile("cp.async.wait_group 1;" ::: "memory"); }
__device__ __forceinline__ void cpa_wait0()  { asm volatile("cp.async.wait_group 0;" ::: "memory"); }

__device__ __forceinline__ float silu(float g) { return g / (1.0f + __expf(-g)); }

__device__ __forceinline__ int find_tile(int t, int* e_out, int* m0_out, int* cnt_out) {
    int acc = 0;
#pragma unroll
    for (int e = 0; e < NUM_EXPERTS; e++) {
        int c = g_counts[e];
        int nt = (c + 127) >> 7;
        if (t < acc + nt) { *e_out = e; *m0_out = (t - acc) << 7; *cnt_out = c; return 1; }
        acc += nt;
    }
    return 0;
}

// ---------------- routing ----------------
__global__ void detect_kernel(const int* __restrict__ t32) {
    if (threadIdx.x == 0) {
        int all_zero = 1;
        for (int i = 0; i < 256; i++) {
            int idx = 2 * (i * (NUM_TOKENS / 256)) + 1;
            if (t32[idx] != 0) { all_zero = 0; break; }
        }
        g_is64 = all_zero;
        g_pwdone = 0;
    }
    if (threadIdx.x < NUM_EXPERTS) g_counts[threadIdx.x] = 0;
    if (threadIdx.x < MAX_TILES) g_t1done[threadIdx.x] = 0;
}

__global__ void route_kernel(const int* __restrict__ t32) {
    int i = blockIdx.x * blockDim.x + threadIdx.x;
    if (i < NUM_TOKENS) {
        int v = g_is64 ? t32[2 * i] : t32[i];
        int e = v & 7;
        int p = atomicAdd(&g_counts[e], 1);
        g_lists[e][p] = i;
    }
}

// ---------------- prep bodies (no dynamic smem) ----------------
__device__ void pack_w1_body(const float* __restrict__ gup, int bx, int nt, int e) {
    const int tid = threadIdx.x;
    const int w = tid >> 5, lane = tid & 31;
    const int g = lane >> 2, tq = lane & 3;
    const int kf = bx * 8 + w;             // 0..255
    const float* W = gup + (size_t)e * HIDDEN * GU_COLS;
    const int k0 = kf * 16 + tq * 2;
#pragma unroll
    for (int i = 0; i < 16; i++) {
        int gu = i >> 3, nf = i & 7;
        int c = gu * INTER + nt * 64 + nf * 8 + g;
        const float* Wc = W + c;
        uint2 o;
        o.x = f2h2(Wc[(size_t)k0 * GU_COLS], Wc[(size_t)(k0 + 1) * GU_COLS]);
        o.y = f2h2(Wc[(size_t)(k0 + 8) * GU_COLS], Wc[(size_t)(k0 + 9) * GU_COLS]);
        size_t off = ((((((size_t)e * 32 + nt) * 256 + kf) * 2 + gu) * 8 + nf) * 32 + lane) * 2;
        *(uint2*)(g_wp1 + off) = o;
    }
}

// smem-free pack_x: direct gmem gather into fragment layout.
// Lanes with equal g cover full 32B sectors (4 tq x float2).
__device__ void pack_x_body(const float* __restrict__ x, int* tokS, int kb, int tile) {
    int e, m0, count;
    if (!find_tile(tile, &e, &m0, &count)) return;
    const int tid = threadIdx.x;
    const int w = tid >> 5, lane = tid & 31;
    const int g = lane >> 2, tq = lane & 3;
    if (tid < 128) tokS[tid] = (m0 + tid < count) ? g_lists[e][m0 + tid] : -1;
    __syncthreads();
    const int kf = kb * 8 + w;
    const int c0 = kf * 16 + 2 * tq;
    const float2 zero = make_float2(0.f, 0.f);
#pragma unroll
    for (int mf = 0; mf < 8; mf++) {
        int r0 = mf * 16 + g;
        int t0 = tokS[r0], t1 = tokS[r0 + 8];
        float2 v00 = zero, v01 = zero, v10 = zero, v11 = zero;
        if (t0 >= 0) {
            const float* p0 = x + (size_t)t0 * HIDDEN + c0;
            v00 = *(const float2*)p0;
            v01 = *(const float2*)(p0 + 8);
        }
        if (t1 >= 0) {
            const float* p1 = x + (size_t)t1 * HIDDEN + c0;
            v10 = *(const float2*)p1;
            v11 = *(const float2*)(p1 + 8);
        }
        uint4 o;
        o.x = f2h2(v00.x, v00.y);
        o.y = f2h2(v10.x, v10.y);
        o.z = f2h2(v01.x, v01.y);
        o.w = f2h2(v11.x, v11.y);
        size_t off = ((((size_t)tile * (HIDDEN / 16) + kf) * 8 + mf) * 32 + lane) * 4;
        *(uint4*)(g_xpackh + off) = o;
    }
}

// fused prep: pack_w1 + pack_x share the grid, both DRAM-bound, no smem tax
__global__ __launch_bounds__(256) void prep_kernel(const float* __restrict__ gup,
                                                   const float* __restrict__ x) {
    __shared__ int tokS[128];
    const int fid = blockIdx.x;
    if (fid < PW1_BLOCKS) {
        pack_w1_body(gup, fid & 31, (fid >> 5) & 31, fid >> 10);
    } else {
        const int idx = fid - PW1_BLOCKS;
        pack_x_body(x, tokS, idx & 31, idx >> 5);
    }
}

// smem: per stage [A 16KB][B 16KB], BK=64 (4 kf16)
#define STAGE_BYTES 32768
#define GEMM_SMEM (NSTAGE * STAGE_BYTES)   /* 98304 */

// ---------------- mega kernel bodies ----------------
__device__ void pack_w2_body(const float* __restrict__ down, int idx) {
    const int bx = idx & 15, nt = (idx >> 4) & 31, e = idx >> 9;
    const int tid = threadIdx.x;
    const int w = tid >> 5, lane = tid & 31;
    const int g = lane >> 2, tq = lane & 3;
    const int kf = bx * 8 + w;             // 0..127
    const float* W = down + (size_t)e * INTER * HIDDEN;
    const int k0 = kf * 16 + tq * 2;
#pragma unroll
    for (int nf = 0; nf < 16; nf++) {
        int c = nt * 128 + nf * 8 + g;
        const float* Wc = W + c;
        uint2 o;
        o.x = f2h2(Wc[(size_t)k0 * HIDDEN], Wc[(size_t)(k0 + 1) * HIDDEN]);
        o.y = f2h2(Wc[(size_t)(k0 + 8) * HIDDEN], Wc[(size_t)(k0 + 9) * HIDDEN]);
        size_t off = (((((size_t)e * 32 + nt) * 128 + kf) * 16 + nf) * 32 + lane) * 2;
        *(uint2*)(g_wp2 + off) = o;
    }
    __threadfence();
    __syncthreads();
    if (tid == 0) atomicAdd(&g_pwdone, 1);
}

__device__ void gemm1_body(char* smem, int nt, int t_id) {
    int e, m0, count;
    if (!find_tile(t_id, &e, &m0, &count)) return;

    const uint32_t sb = smem_u32(smem);
    const int tid = threadIdx.x;
    const int wid = tid >> 5, lane = tid & 31;
    const int mw = wid >> 2, nw = wid & 3;
    const int g = lane >> 2, tq = lane & 3;

    const uint32_t* xA = g_xpackh + (size_t)t_id * (HIDDEN / 16) * 1024;
    const uint32_t* wB = g_wp1 + (((size_t)e * 32 + nt) * 256) * 1024;

    auto issue = [&](int kc, int soff) {
        const uint32_t* As = xA + (size_t)kc * 4096;
        const uint32_t* Bs = wB + (size_t)kc * 4096;
#pragma unroll
        for (int j = 0; j < 4; j++) {
            int idx = tid + j * 256;
            cpa16(sb + soff + idx * 16, As + idx * 4);
            cpa16(sb + soff + 16384 + idx * 16, Bs + idx * 4);
        }
    };

    float accg[4][2][4] = {};
    float accu[4][2][4] = {};

    issue(0, 0);
    cpa_commit();
    issue(1, STAGE_BYTES);
    cpa_commit();

    const int NK = HIDDEN / 64;
    int soff_c = 0, soff_p = 2 * STAGE_BYTES;
    for (int kc = 0; kc < NK; kc++) {
        if (kc + 1 < NK) cpa_wait1(); else cpa_wait0();
        __syncthreads();
        if (kc + 2 < NK) {
            issue(kc + 2, soff_p);
            cpa_commit();
        }

#pragma unroll
        for (int kk = 0; kk < 4; kk++) {
            uint2 bg[2], bu[2];
#pragma unroll
            for (int ni = 0; ni < 2; ni++) {
                bg[ni] = *(const uint2*)(smem + soff_c + 16384 +
                            ((kk * 2 + 0) * 8 + nw * 2 + ni) * 256 + lane * 8);
                bu[ni] = *(const uint2*)(smem + soff_c + 16384 +
                            ((kk * 2 + 1) * 8 + nw * 2 + ni) * 256 + lane * 8);
            }
#pragma unroll
            for (int mi = 0; mi < 4; mi++) {
                const uint4 a = *(const uint4*)(smem + soff_c +
                            ((kk * 8 + mw * 4 + mi) * 32 + lane) * 16);
                mma16(accg[mi][0], &a.x, bg[0].x, bg[0].y);
                mma16(accg[mi][1], &a.x, bg[1].x, bg[1].y);
                mma16(accu[mi][0], &a.x, bu[0].x, bu[0].y);
                mma16(accu[mi][1], &a.x, bu[1].x, bu[1].y);
            }
        }
        soff_c += STAGE_BYTES; if (soff_c == NSTAGE * STAGE_BYTES) soff_c = 0;
        soff_p += STAGE_BYTES; if (soff_p == NSTAGE * STAGE_BYTES) soff_p = 0;
    }

    const int kf = nt * 4 + nw;
#pragma unroll
    for (int mi = 0; mi < 4; mi++) {
        int mf = mw * 4 + mi;
        uint4 o;
        {
            float v0 = silu(accg[mi][0][0]) * accu[mi][0][0];
            float v1 = silu(accg[mi][0][1]) * accu[mi][0][1];
            float v2 = silu(accg[mi][0][2]) * accu[mi][0][2];
            float v3 = silu(accg[mi][0][3]) * accu[mi][0][3];
            o.x = f2h2(v0, v1);
            o.y = f2h2(v2, v3);
        }
        {
            float v0 = silu(accg[mi][1][0]) * accu[mi][1][0];
            float v1 = silu(accg[mi][1][1]) * accu[mi][1][1];
            float v2 = silu(accg[mi][1][2]) * accu[mi][1][2];
            float v3 = silu(accg[mi][1][3]) * accu[mi][1][3];
            o.z = f2h2(v0, v1);
            o.w = f2h2(v2, v3);
        }
        size_t off = ((((size_t)t_id * (INTER / 16) + kf) * 8 + mf) * 32 + (g * 4 + tq)) * 4;
        *(uint4*)(g_interph + off) = o;
    }

    __threadfence();
    __syncthreads();
    if (tid == 0) atomicAdd(&g_t1done[t_id], 1);
}

__device__ void gemm2_body(char* smem, int* tokS, float* __restrict__ out, int nt, int t_id) {
    int e, m0, count;
    if (!find_tile(t_id, &e, &m0, &count)) return;
    const int n0 = nt * 128;

    const uint32_t sb = smem_u32(smem);
    const int tid = threadIdx.x;
    const int wid = tid >> 5, lane = tid & 31;
    const int mw = wid >> 2, nw = wid & 3;
    const int g = lane >> 2, tq = lane & 3;

    if (tid == 0) {
        while (atomicAdd(&g_pwdone, 0) < PW2_BLOCKS) {}
        while (atomicAdd(&g_t1done[t_id], 0) < 32) {}
        __threadfence();
    }
    __syncthreads();
    if (tid < 128) tokS[tid] = (m0 + tid < count) ? g_lists[e][m0 + tid] : -1;
    __syncthreads();

    const uint32_t* xA = g_interph + (size_t)t_id * (INTER / 16) * 1024;
    const uint32_t* wB = g_wp2 + (((size_t)e * 32 + nt) * 128) * 1024;

    auto issue = [&](int kc, int soff) {
        const uint32_t* As = xA + (size_t)kc * 4096;
        const uint32_t* Bs = wB + (size_t)kc * 4096;
#pragma unroll
        for (int j = 0; j < 4; j++) {
            int idx = tid + j * 256;
            cpa16(sb + soff + idx * 16, As + idx * 4);
            cpa16(sb + soff + 16384 + idx * 16, Bs + idx * 4);
        }
    };

    float acc[4][4][4] = {};

    issue(0, 0);
    cpa_commit();
    issue(1, STAGE_BYTES);
    cpa_commit();

    const int NK = INTER / 64;
    int soff_c = 0, soff_p = 2 * STAGE_BYTES;
    for (int kc = 0; kc < NK; kc++) {
        if (kc + 1 < NK) cpa_wait1(); else cpa_wait0();
        __syncthreads();
        if (kc + 2 < NK) {
            issue(kc + 2, soff_p);
            cpa_commit();
        }

#pragma unroll
        for (int kk = 0; kk < 4; kk++) {
            uint2 bb[4];
#pragma unroll
            for (int ni = 0; ni < 4; ni++)
                bb[ni] = *(const uint2*)(smem + soff_c + 16384 +
                            (kk * 16 + nw * 4 + ni) * 256 + lane * 8);
#pragma unroll
            for (int mi = 0; mi < 4; mi++) {
                const uint4 a = *(const uint4*)(smem + soff_c +
                            ((kk * 8 + mw * 4 + mi) * 32 + lane) * 16);
#pragma unroll
                for (int ni = 0; ni < 4; ni++)
                    mma16(acc[mi][ni], &a.x, bb[ni].x, bb[ni].y);
            }
        }
        soff_c += STAGE_BYTES; if (soff_c == NSTAGE * STAGE_BYTES) soff_c = 0;
        soff_p += STAGE_BYTES; if (soff_p == NSTAGE * STAGE_BYTES) soff_p = 0;
    }

#pragma unroll
    for (int mi = 0; mi < 4; mi++) {
        int r0 = mw * 64 + mi * 16 + g;
        int t0 = tokS[r0], t1 = tokS[r0 + 8];
#pragma unroll
        for (int ni = 0; ni < 4; ni++) {
            int col = n0 + nw * 32 + ni * 8 + 2 * tq;
            if (t0 >= 0)
                *(float2*)(out + (size_t)t0 * HIDDEN + col) =
                    make_float2(acc[mi][ni][0], acc[mi][ni][1]);
            if (t1 >= 0)
                *(float2*)(out + (size_t)t1 * HIDDEN + col) =
                    make_float2(acc[mi][ni][2], acc[mi][ni][3]);
        }
    }
}

// ---------------- mega kernel: pack_w2 (interleaved with) gemm1, then gemm2 ----------------
__global__ __launch_bounds__(256, 2) void mega_kernel(const float* __restrict__ down,
                                                      float* __restrict__ out) {
    extern __shared__ char smem[];
    __shared__ int tokS[128];
    const int fid = blockIdx.x;
    if (fid < INTERLEAVED) {
        const int grp = fid / 25, r = fid % 25;
        if (r < 9) {
            const int idx = grp * 9 + r;             // 0..2303
            gemm1_body(smem, idx & 31, idx >> 5);
        } else {
            const int idx = grp * 16 + (r - 9);      // 0..4095
            pack_w2_body(down, idx);
        }
    } else {
        const int idx = fid - INTERLEAVED;           // 0..2303
        gemm2_body(smem, tokS, out, idx & 31, idx >> 5);
    }
}

// ---------------- launch ----------------
extern "C" void kernel_launch(void* const* d_in, const int* in_sizes, int n_in,
                              void* d_out, int out_size) {
    const float* x    = (const float*)d_in[0];
    const int*   tids = (const int*)d_in[1];
    const float* gup  = (const float*)d_in[2];
    const float* down = (const float*)d_in[3];
    float*       out  = (float*)d_out;

    cudaFuncSetAttribute(mega_kernel, cudaFuncAttributeMaxDynamicSharedMemorySize, GEMM_SMEM);

    detect_kernel<<<1, 128>>>(tids);
    route_kernel<<<NUM_TOKENS / 256, 256>>>(tids);
    prep_kernel<<<PW1_BLOCKS + PX_BLOCKS, 256>>>(gup, x);
    mega_kernel<<<MEGA_BLOCKS, 256, GEMM_SMEM>>>(down, out);
}